// round 2
// baseline (speedup 1.0000x reference)
#include <cuda_runtime.h>
#include <stdint.h>
#include <math.h>

#define B_ 512
#define T_ 64
#define A_ 32
#define H_ 512
#define E_ 32

typedef unsigned long long u64;

// scratch (no allocation allowed -> device globals)
__device__ float g_M1[E_ * A_ * H_];   // W1@W2_top   (E,32,512)  2 MB
__device__ float g_V[B_ * H_];         // per-batch bias (B,512)  1 MB

#define DEV __device__ __forceinline__

DEV u64 pack2(float x) { u64 r; asm("mov.b64 %0, {%1, %1};" : "=l"(r) : "f"(x)); return r; }
DEV void fma2(u64 &d, u64 a, u64 b) { asm("fma.rn.f32x2 %0, %1, %2, %0;" : "+l"(d) : "l"(a), "l"(b)); }
DEV float2 unpk(u64 a) { float2 f; asm("mov.b64 {%0, %1}, %2;" : "=f"(f.x), "=f"(f.y) : "l"(a)); return f; }

DEV void cp16(void* dst, const void* src) {
    unsigned d = (unsigned)__cvta_generic_to_shared(dst);
    asm volatile("cp.async.cg.shared.global [%0], [%1], 16;" :: "r"(d), "l"(src));
}
DEV void cp_commit() { asm volatile("cp.async.commit_group;"); }
DEV void cp_wait0()  { asm volatile("cp.async.wait_group 0;"); }
DEV void cp_wait1()  { asm volatile("cp.async.wait_group 1;"); }

union F4 { float4 v; float f[4]; u64 u[2]; };

DEV float swishf(float z) { return z / (1.0f + expf(-z)); }

// ---------------------------------------------------------------------------
// Kernel 1: M1[e] = W1[e] @ W2[e, :512, :]     grid(E,4) x 128 threads
// ---------------------------------------------------------------------------
__global__ void __launch_bounds__(128) k_m1(const float* __restrict__ W1,
                                            const float* __restrict__ W2)
{
    __shared__ __align__(16) float w1t[64 * 32];   // [hh][a] transposed tile
    const int e   = blockIdx.x;
    const int tid = threadIdx.x;
    const int j   = blockIdx.y * 128 + tid;

    const float* W1e = W1 + (size_t)e * (A_ * H_);            // [a][h]
    const float* W2e = W2 + (size_t)e * (2 * H_ * H_);        // top rows [h][j]

    u64 acc[16];
    #pragma unroll
    for (int p = 0; p < 16; p++) acc[p] = 0ULL;

    for (int ht = 0; ht < 8; ht++) {               // 64 h-rows per tile
        __syncthreads();
        #pragma unroll
        for (int l = 0; l < 16; l++) {
            int idx = tid + l * 128;               // 2048 elements
            int hh = idx >> 5, a = idx & 31;
            w1t[hh * 32 + a] = W1e[a * H_ + ht * 64 + hh];
        }
        __syncthreads();
        #pragma unroll 4
        for (int hh = 0; hh < 64; hh++) {
            u64 wd = pack2(W2e[(size_t)(ht * 64 + hh) * H_ + j]);
            #pragma unroll
            for (int p = 0; p < 16; p++)
                fma2(acc[p], *(const u64*)&w1t[hh * 32 + 2 * p], wd);
        }
    }
    float* M1e = g_M1 + (size_t)e * (A_ * H_);
    #pragma unroll
    for (int p = 0; p < 16; p++) {
        float2 f = unpk(acc[p]);
        M1e[(size_t)(2 * p) * H_ + j]     = f.x;
        M1e[(size_t)(2 * p + 1) * H_ + j] = f.y;
    }
}

// ---------------------------------------------------------------------------
// Kernel 2: v[b] = b1@W2_top + tau(t_b)@W2_bot + b2    grid(E,4) x 128 threads
// batches grouped by expert so W2_bot columns are read once per 8-batch pass
// ---------------------------------------------------------------------------
__global__ void __launch_bounds__(128) k_v(const float* __restrict__ ts,
                                           const int*   __restrict__ cat,
                                           const float* __restrict__ W2,
                                           const float* __restrict__ b1,
                                           const float* __restrict__ b2)
{
    __shared__ int list[B_];
    __shared__ int n;
    __shared__ __align__(16) float trig[512 * 8];   // [k][i] for 8 batches

    const int e   = blockIdx.x;
    const int tid = threadIdx.x;
    const int j   = blockIdx.y * 128 + tid;

    if (tid == 0) n = 0;
    __syncthreads();
    for (int b = tid; b < B_; b += 128)
        if (cat[b] == e) { int p = atomicAdd(&n, 1); list[p] = b; }

    int nzl = 0;
    for (int h = tid; h < H_; h += 128) nzl |= (b1[e * H_ + h] != 0.0f);
    const int nz = __syncthreads_or(nzl);          // also a barrier for list/n
    const int nb = n;
    if (nb == 0) return;

    const float* W2e = W2 + (size_t)e * (2 * H_ * H_);
    float cb = b2[e * H_ + j];
    if (nz) {
        #pragma unroll 8
        for (int h = 0; h < H_; h++)
            cb += b1[e * H_ + h] * W2e[(size_t)h * H_ + j];
    }

    const float L = 9.210340371976184f / 256.0f;   // ln(1e4)/256
    const float* W2bot = W2e + (size_t)H_ * H_;

    for (int bg = 0; bg * 8 < nb; bg++) {
        const int m = min(8, nb - bg * 8);
        __syncthreads();
        for (int idx = tid; idx < 8 * 512; idx += 128) {
            int k = idx >> 3, i = idx & 7;
            int bidx = bg * 8 + i;
            float t = (i < m) ? ts[list[bidx]] : 0.0f;
            int f = k & 255;
            float ang = t * expf(-L * (float)f);
            trig[k * 8 + i] = (k < 256) ? sinf(ang) : cosf(ang);
        }
        __syncthreads();

        float acc[8];
        #pragma unroll
        for (int i = 0; i < 8; i++) acc[i] = 0.0f;

        #pragma unroll 4
        for (int k = 0; k < 512; k++) {
            float w = W2bot[(size_t)k * H_ + j];
            float4 t0 = *(const float4*)&trig[k * 8];
            float4 t1 = *(const float4*)&trig[k * 8 + 4];
            acc[0] += t0.x * w; acc[1] += t0.y * w;
            acc[2] += t0.z * w; acc[3] += t0.w * w;
            acc[4] += t1.x * w; acc[5] += t1.y * w;
            acc[6] += t1.z * w; acc[7] += t1.w * w;
        }
        for (int i = 0; i < m; i++)
            g_V[(size_t)list[bg * 8 + i] * H_ + j] = acc[i] + cb;
    }
}

// ---------------------------------------------------------------------------
// 16-k-step microkernel: acc[8 rows][16 cols as 8 f32x2] += y-tile * w-tile
// wb: [16][512] SMEM; yb: row base with stride ystride, 16 k's at offset 0
// ---------------------------------------------------------------------------
DEV void mma16(const float* __restrict__ wb, const float* __restrict__ yb,
               int ystride, u64 (&acc)[8][8], int t0, int jb)
{
    #pragma unroll
    for (int k4 = 0; k4 < 4; k4++) {
        F4 yv[8];
        #pragma unroll
        for (int r = 0; r < 8; r++)
            yv[r].v = *(const float4*)&yb[(t0 + r) * ystride + k4 * 4];
        #pragma unroll
        for (int kk = 0; kk < 4; kk++) {
            F4 wv[4];
            #pragma unroll
            for (int c = 0; c < 4; c++)
                wv[c].v = *(const float4*)&wb[(k4 * 4 + kk) * 512 + jb + 128 * c];
            #pragma unroll
            for (int r = 0; r < 8; r++) {
                u64 yd = pack2(yv[r].f[kk]);
                #pragma unroll
                for (int c = 0; c < 4; c++) {
                    fma2(acc[r][2 * c],     yd, wv[c].u[0]);
                    fma2(acc[r][2 * c + 1], yd, wv[c].u[1]);
                }
            }
        }
    }
}

// ---------------------------------------------------------------------------
// Main kernel: one CTA per batch (grid=512, 256 threads, 1 CTA/SM)
//   y = swish(actions[b] @ M1[e] + v[b])     (64x512, in SMEM)
//   out[b] = y @ W3[e] + b3[e]               (64x512x512 f32x2 FMAs)
// ---------------------------------------------------------------------------
__global__ void __launch_bounds__(256, 1) k_main(const float* __restrict__ actions,
                                                 const int*   __restrict__ cat_ids,
                                                 const float* __restrict__ W3,
                                                 const float* __restrict__ b3,
                                                 float*       __restrict__ out)
{
    extern __shared__ float sm[];
    float* ys  = sm;               // 64*512  y activations (128 KB)
    float* ws  = sm + 64 * 512;    // 2 x 16*512 tile buffers (64 KB)
    float* act = ws + 32 * 512;    // 64*32 actions (8 KB)

    const int tid = threadIdx.x;
    const int b   = blockIdx.x;
    const int e   = cat_ids[b];
    const int t0  = (tid >> 5) * 8;      // 8 rows / thread, warp-uniform
    const int jb  = (tid & 31) * 4;      // cols jb + 128c + {0..3}, c=0..3

    // ---- stage M1[e] (32x512 -> both tile buffers) and actions[b] ----
    const float* M1e  = g_M1 + (size_t)e * (A_ * H_);
    const float* actb = actions + (size_t)b * (T_ * A_);
    #pragma unroll
    for (int l = 0; l < 16; l++) {
        int idx = tid + l * 256;                   // 4096 float4 chunks
        int r = idx >> 7, c4 = (idx & 127) << 2;
        cp16(ws + r * 512 + c4, M1e + (size_t)r * 512 + c4);
    }
    #pragma unroll
    for (int l = 0; l < 2; l++) {
        int idx = (tid + l * 256) << 2;            // 2048 floats
        cp16(act + idx, actb + idx);
    }
    cp_commit();
    cp_wait0();
    __syncthreads();

    u64 acc[8][8];
    #pragma unroll
    for (int r = 0; r < 8; r++)
        #pragma unroll
        for (int c = 0; c < 8; c++) acc[r][c] = 0ULL;

    // ---- layer 1: z = actions @ M1  (K = 32, two 16-k halves) ----
    mma16(ws,            act,      32, acc, t0, jb);
    mma16(ws + 16 * 512, act + 16, 32, acc, t0, jb);

    // ---- + v, swish, write y to SMEM ----
    {
        const float* vb = g_V + (size_t)b * H_;
        F4 vv[4];
        #pragma unroll
        for (int c = 0; c < 4; c++)
            vv[c].v = *(const float4*)&vb[jb + 128 * c];
        #pragma unroll
        for (int r = 0; r < 8; r++) {
            #pragma unroll
            for (int c = 0; c < 4; c++) {
                float2 lo = unpk(acc[r][2 * c]);
                float2 hi = unpk(acc[r][2 * c + 1]);
                float4 o;
                o.x = swishf(lo.x + vv[c].f[0]);
                o.y = swishf(lo.y + vv[c].f[1]);
                o.z = swishf(hi.x + vv[c].f[2]);
                o.w = swishf(hi.y + vv[c].f[3]);
                *(float4*)&ys[(t0 + r) * 512 + jb + 128 * c] = o;
                acc[r][2 * c] = 0ULL; acc[r][2 * c + 1] = 0ULL;
            }
        }
    }
    __syncthreads();   // ys visible; wbuf reads done before overwrite

    // ---- layer 2: out = y @ W3[e] + b3, W3 streamed 16 rows/tile ----
    const float* W3e = W3 + (size_t)e * (H_ * H_);

    // prefetch tile 0
    #pragma unroll
    for (int l = 0; l < 8; l++) {
        int idx = tid + l * 256;                   // 2048 float4 chunks
        int r = idx >> 7, c4 = (idx & 127) << 2;
        cp16(ws + r * 512 + c4, W3e + (size_t)r * 512 + c4);
    }
    cp_commit();

    for (int kt = 0; kt < 32; kt++) {
        if (kt < 31) {
            const float* src = W3e + (size_t)(kt + 1) * 16 * 512;
            float* dst = ws + ((kt + 1) & 1) * 16 * 512;
            #pragma unroll
            for (int l = 0; l < 8; l++) {
                int idx = tid + l * 256;
                int r = idx >> 7, c4 = (idx & 127) << 2;
                cp16(dst + r * 512 + c4, src + (size_t)r * 512 + c4);
            }
            cp_commit();
            cp_wait1();
        } else {
            cp_wait0();
        }
        __syncthreads();
        mma16(ws + (kt & 1) * 16 * 512, ys + kt * 16, 512, acc, t0, jb);
        __syncthreads();
    }

    // ---- epilogue: + b3, store ----
    {
        const float* b3e = b3 + (size_t)e * H_;
        F4 bv[4];
        #pragma unroll
        for (int c = 0; c < 4; c++)
            bv[c].v = *(const float4*)&b3e[jb + 128 * c];
        float* outb = out + (size_t)b * (T_ * H_);
        #pragma unroll
        for (int r = 0; r < 8; r++) {
            #pragma unroll
            for (int c = 0; c < 4; c++) {
                float2 lo = unpk(acc[r][2 * c]);
                float2 hi = unpk(acc[r][2 * c + 1]);
                float4 o;
                o.x = lo.x + bv[c].f[0];
                o.y = lo.y + bv[c].f[1];
                o.z = hi.x + bv[c].f[2];
                o.w = hi.y + bv[c].f[3];
                *(float4*)&outb[(size_t)(t0 + r) * 512 + jb + 128 * c] = o;
            }
        }
    }
}

// ---------------------------------------------------------------------------
extern "C" void kernel_launch(void* const* d_in, const int* in_sizes, int n_in,
                              void* d_out, int out_size)
{
    const float* actions = (const float*)d_in[0];
    const float* ts      = (const float*)d_in[1];
    const int*   cat     = (const int*)  d_in[2];
    const float* W1      = (const float*)d_in[3];
    const float* b1      = (const float*)d_in[4];
    const float* W2      = (const float*)d_in[5];
    const float* b2      = (const float*)d_in[6];
    const float* W3      = (const float*)d_in[7];
    const float* b3      = (const float*)d_in[8];
    float*       out     = (float*)d_out;

    const int smem_main = (64 * 512 + 32 * 512 + 64 * 32) * 4;  // 200 KB
    cudaFuncSetAttribute(k_main, cudaFuncAttributeMaxDynamicSharedMemorySize, smem_main);

    k_m1  <<<dim3(E_, 4), 128>>>(W1, W2);
    k_v   <<<dim3(E_, 4), 128>>>(ts, cat, W2, b1, b2);
    k_main<<<B_, 256, smem_main>>>(actions, cat, W3, b3, out);
}

// round 3
// speedup vs baseline: 1.3440x; 1.3440x over previous
#include <cuda_runtime.h>
#include <stdint.h>
#include <math.h>

#define B_ 512
#define T_ 64
#define A_ 32
#define H_ 512
#define E_ 32

typedef unsigned long long u64;

// scratch (no allocation allowed -> device globals)
__device__ float g_M1[E_ * A_ * H_];   // W1@W2_top   (E,32,512)  2 MB
__device__ float g_V[B_ * H_];         // per-batch bias (B,512)  1 MB

#define DEV __device__ __forceinline__

DEV u64 pack2(float x) { u64 r; asm("mov.b64 %0, {%1, %1};" : "=l"(r) : "f"(x)); return r; }
DEV void fma2(u64 &d, u64 a, u64 b) { asm("fma.rn.f32x2 %0, %1, %2, %0;" : "+l"(d) : "l"(a), "l"(b)); }
DEV float2 unpk(u64 a) { float2 f; asm("mov.b64 {%0, %1}, %2;" : "=f"(f.x), "=f"(f.y) : "l"(a)); return f; }

DEV void cp16(void* dst, const void* src) {
    unsigned d = (unsigned)__cvta_generic_to_shared(dst);
    asm volatile("cp.async.cg.shared.global [%0], [%1], 16;" :: "r"(d), "l"(src));
}
DEV void cp_commit() { asm volatile("cp.async.commit_group;"); }
DEV void cp_wait0()  { asm volatile("cp.async.wait_group 0;"); }

union F4 { float4 v; float f[4]; u64 u[2]; };

DEV float swishf(float z) { return z / (1.0f + expf(-z)); }

// ---------------------------------------------------------------------------
// Kernel 1: M1[e] = W1[e] @ W2[e, :512, :]   grid(E,4) x 128 threads
// W2_top column slice streamed via cp.async double buffer (32k x 128j tiles)
// ---------------------------------------------------------------------------
__global__ void __launch_bounds__(128) k_m1(const float* __restrict__ W1,
                                            const float* __restrict__ W2)
{
    extern __shared__ float sm1[];
    float* w1t = sm1;                      // [512][34] padded transpose of W1e
    float* wt  = sm1 + 512 * 34;           // 2 x [32][128] W2 tiles

    const int e   = blockIdx.x;
    const int tid = threadIdx.x;
    const int j0  = blockIdx.y * 128;
    const int j   = j0 + tid;

    const float* W1e = W1 + e * (A_ * H_);            // [a][h]
    const float* W2e = W2 + e * (2 * H_ * H_) + j0;   // top rows, our j slice

    // prefetch tile 0 (overlaps w1t staging)
    #pragma unroll
    for (int l = 0; l < 8; l++) {
        int idx = tid + l * 128;           // 1024 float4 chunks
        int r = idx >> 5, c4 = (idx & 31) << 2;
        cp16(wt + r * 128 + c4, W2e + r * H_ + c4);
    }
    cp_commit();

    // stage W1e transposed: w1t[h][a] with stride 34 (even pad -> 8B aligned)
    for (int idx = tid; idx < A_ * H_; idx += 128) {
        int a = idx >> 9, hh = idx & 511;  // coalesced reads along hh
        w1t[hh * 34 + a] = W1e[a * H_ + hh];
    }

    u64 acc[16];
    #pragma unroll
    for (int p = 0; p < 16; p++) acc[p] = 0ULL;

    for (int kt = 0; kt < 16; kt++) {
        cp_wait0();
        __syncthreads();
        if (kt < 15) {
            const float* src = W2e + (kt + 1) * 32 * H_;
            float* dst = wt + ((kt + 1) & 1) * (32 * 128);
            #pragma unroll
            for (int l = 0; l < 8; l++) {
                int idx = tid + l * 128;
                int r = idx >> 5, c4 = (idx & 31) << 2;
                cp16(dst + r * 128 + c4, src + r * H_ + c4);
            }
            cp_commit();
        }
        const float* cur = wt + (kt & 1) * (32 * 128);
        #pragma unroll 2
        for (int hl = 0; hl < 32; hl++) {
            const int hh = kt * 32 + hl;
            u64 wd = pack2(cur[hl * 128 + tid]);
            #pragma unroll
            for (int p = 0; p < 16; p++)
                fma2(acc[p], *(const u64*)&w1t[hh * 34 + 2 * p], wd);
        }
        __syncthreads();
    }
    float* M1e = g_M1 + e * (A_ * H_);
    #pragma unroll
    for (int p = 0; p < 16; p++) {
        float2 f = unpk(acc[p]);
        M1e[(2 * p) * H_ + j]     = f.x;
        M1e[(2 * p + 1) * H_ + j] = f.y;
    }
}

// ---------------------------------------------------------------------------
// Kernel 2: v[b] = b1@W2_top + tau(t_b)@W2_bot + b2   grid(E,4) x 128 threads
// 16 batches per pass; W2_bot slice streamed via cp.async double buffer
// ---------------------------------------------------------------------------
__global__ void __launch_bounds__(128) k_v(const float* __restrict__ ts,
                                           const int*   __restrict__ cat,
                                           const float* __restrict__ W2,
                                           const float* __restrict__ b1,
                                           const float* __restrict__ b2)
{
    __shared__ int list[B_];
    __shared__ int n;
    extern __shared__ float smv[];
    float* trig = smv;                     // [512][16]
    float* wt   = smv + 512 * 16;          // 2 x [32][128]

    const int e   = blockIdx.x;
    const int tid = threadIdx.x;
    const int j0  = blockIdx.y * 128;
    const int j   = j0 + tid;

    if (tid == 0) n = 0;
    __syncthreads();
    for (int b = tid; b < B_; b += 128)
        if (cat[b] == e) { int p = atomicAdd(&n, 1); list[p] = b; }

    int nzl = 0;
    for (int h = tid; h < H_; h += 128) nzl |= (b1[e * H_ + h] != 0.0f);
    const int nz = __syncthreads_or(nzl);   // also publishes list/n
    const int nb = n;

    const float* W2e = W2 + e * (2 * H_ * H_);
    float cb = b2[e * H_ + j];
    if (nz) {
        #pragma unroll 8
        for (int h = 0; h < H_; h++)
            cb += b1[e * H_ + h] * W2e[h * H_ + j];
    }

    const float L = 9.210340371976184f / 256.0f;   // ln(1e4)/256
    const float* W2bot = W2e + H_ * H_ + j0;

    for (int bg = 0; bg * 16 < nb; bg++) {
        const int m = min(16, nb - bg * 16);
        __syncthreads();
        for (int idx = tid; idx < 16 * 512; idx += 128) {
            int k = idx >> 4, i = idx & 15;
            float t = (i < m) ? ts[list[bg * 16 + i]] : 0.0f;
            float ang = t * expf(-L * (float)(k & 255));
            trig[k * 16 + i] = (k < 256) ? sinf(ang) : cosf(ang);
        }
        // prefetch W2bot tile 0
        #pragma unroll
        for (int l = 0; l < 8; l++) {
            int idx = tid + l * 128;
            int r = idx >> 5, c4 = (idx & 31) << 2;
            cp16(wt + r * 128 + c4, W2bot + r * H_ + c4);
        }
        cp_commit();

        float acc[16];
        #pragma unroll
        for (int i = 0; i < 16; i++) acc[i] = 0.0f;

        for (int kt = 0; kt < 16; kt++) {
            cp_wait0();
            __syncthreads();
            if (kt < 15) {
                const float* src = W2bot + (kt + 1) * 32 * H_;
                float* dst = wt + ((kt + 1) & 1) * (32 * 128);
                #pragma unroll
                for (int l = 0; l < 8; l++) {
                    int idx = tid + l * 128;
                    int r = idx >> 5, c4 = (idx & 31) << 2;
                    cp16(dst + r * 128 + c4, src + r * H_ + c4);
                }
                cp_commit();
            }
            const float* cur = wt + (kt & 1) * (32 * 128);
            #pragma unroll 2
            for (int kk = 0; kk < 32; kk++) {
                const int k = kt * 32 + kk;
                float w = cur[kk * 128 + tid];
                F4 t0, t1, t2, t3;
                t0.v = *(const float4*)&trig[k * 16];
                t1.v = *(const float4*)&trig[k * 16 + 4];
                t2.v = *(const float4*)&trig[k * 16 + 8];
                t3.v = *(const float4*)&trig[k * 16 + 12];
                #pragma unroll
                for (int q = 0; q < 4; q++) {
                    acc[q]      += t0.f[q] * w;
                    acc[4 + q]  += t1.f[q] * w;
                    acc[8 + q]  += t2.f[q] * w;
                    acc[12 + q] += t3.f[q] * w;
                }
            }
            __syncthreads();
        }
        for (int i = 0; i < m; i++)
            g_V[list[bg * 16 + i] * H_ + j] = acc[i] + cb;
    }
}

// ---------------------------------------------------------------------------
// main kernel helpers
// ---------------------------------------------------------------------------
// acc[8 rows][4 f32x2] covers 8 rows x 8 cols (jb + {0..3}, jb+128+{0..3})
DEV void mma_tile(const float* __restrict__ wb /*[16][256]*/,
                  const float* __restrict__ yrow, int ystride,
                  u64 (&acc)[8][4], int t0, int jb)
{
    #pragma unroll
    for (int k4 = 0; k4 < 4; k4++) {
        F4 yv[8];
        #pragma unroll
        for (int r = 0; r < 8; r++)
            yv[r].v = *(const float4*)&yrow[(t0 + r) * ystride + k4 * 4];
        #pragma unroll
        for (int kk = 0; kk < 4; kk++) {
            F4 w0, w1;
            w0.v = *(const float4*)&wb[(k4 * 4 + kk) * 256 + jb];
            w1.v = *(const float4*)&wb[(k4 * 4 + kk) * 256 + jb + 128];
            #pragma unroll
            for (int r = 0; r < 8; r++) {
                u64 yd = pack2(yv[r].f[kk]);
                fma2(acc[r][0], yd, w0.u[0]);
                fma2(acc[r][1], yd, w0.u[1]);
                fma2(acc[r][2], yd, w1.u[0]);
                fma2(acc[r][3], yd, w1.u[1]);
            }
        }
    }
}

// ---------------------------------------------------------------------------
// Main kernel: grid (B, 2), 256 threads. CTA (b, jsel) computes full
//   y = swish(actions[b] @ M1[e] + v[b])   (64x512, SMEM; layer-1 duplicated)
// then its 256-column half of  out[b] = y @ W3[e] + b3[e].
// Weight tiles (16k x 256j) stream through a cp.async double buffer,
// one barrier per tile.
// ---------------------------------------------------------------------------
__global__ void __launch_bounds__(256, 1) k_main(const float* __restrict__ actions,
                                                 const int*   __restrict__ cat_ids,
                                                 const float* __restrict__ W3,
                                                 const float* __restrict__ b3,
                                                 float*       __restrict__ out)
{
    extern __shared__ float sm[];
    float* ys  = sm;                    // 64*512   (128 KB)
    float* wt  = sm + 64 * 512;         // 2 x 16*256 (32 KB)
    float* act = wt + 2 * 16 * 256;     // 64*32    (8 KB)

    const int tid  = threadIdx.x;
    const int b    = blockIdx.x;
    const int jsel = blockIdx.y;
    const int e    = cat_ids[b];
    const int t0   = (tid >> 5) * 8;    // 8 rows / thread (warp-uniform)
    const int jb   = (tid & 31) * 4;    // cols jb + {0..3}, jb+128+{0..3}

    const float* M1e  = g_M1 + e * (A_ * H_);
    const float* actb = actions + b * (T_ * A_);
    const float* W3e  = W3 + e * (H_ * H_);

    // tile g: g<4 -> M1[kh=g&1][jh=g>>1];  g>=4 -> W3 row-tile (g-4), jsel half
    #define ISSUE(g) do {                                                       \
        const float* _s = ((g) < 4)                                             \
            ? (M1e + ((g) & 1) * (16 * H_) + ((g) >> 1) * 256)                   \
            : (W3e + ((g) - 4) * (16 * H_) + jsel * 256);                        \
        float* _d = wt + ((g) & 1) * (16 * 256);                                 \
        _Pragma("unroll")                                                        \
        for (int _l = 0; _l < 4; _l++) {                                         \
            int _i = tid + _l * 256;                                             \
            int _r = _i >> 6, _c = (_i & 63) << 2;                               \
            cp16(_d + _r * 256 + _c, _s + _r * H_ + _c);                         \
        }                                                                        \
        cp_commit();                                                             \
    } while (0)

    // prologue: actions + tile 0 in one group
    #pragma unroll
    for (int l = 0; l < 2; l++) {
        int idx = (tid + l * 256) << 2;
        cp16(act + idx, actb + idx);
    }
    ISSUE(0);

    u64 acc[8][4];
    #pragma unroll
    for (int r = 0; r < 8; r++)
        #pragma unroll
        for (int c = 0; c < 4; c++) acc[r][c] = 0ULL;

    // ---- layer 1: 4 tiles (jh = g>>1, kh = g&1) ----
    #pragma unroll
    for (int g = 0; g < 4; g++) {
        cp_wait0();
        __syncthreads();
        ISSUE(g + 1);
        mma_tile(wt + (g & 1) * (16 * 256), act + (g & 1) * 16, 32, acc, t0, jb);
        if (g & 1) {
            const int jh = g >> 1;
            const float* vb = g_V + b * H_ + jh * 256;
            F4 v0, v1;
            v0.v = *(const float4*)&vb[jb];
            v1.v = *(const float4*)&vb[jb + 128];
            #pragma unroll
            for (int r = 0; r < 8; r++) {
                float2 a0 = unpk(acc[r][0]), a1 = unpk(acc[r][1]);
                float2 a2 = unpk(acc[r][2]), a3 = unpk(acc[r][3]);
                float4 o0, o1;
                o0.x = swishf(a0.x + v0.f[0]); o0.y = swishf(a0.y + v0.f[1]);
                o0.z = swishf(a1.x + v0.f[2]); o0.w = swishf(a1.y + v0.f[3]);
                o1.x = swishf(a2.x + v1.f[0]); o1.y = swishf(a2.y + v1.f[1]);
                o1.z = swishf(a3.x + v1.f[2]); o1.w = swishf(a3.y + v1.f[3]);
                *(float4*)&ys[(t0 + r) * 512 + jh * 256 + jb]       = o0;
                *(float4*)&ys[(t0 + r) * 512 + jh * 256 + jb + 128] = o1;
                acc[r][0] = acc[r][1] = acc[r][2] = acc[r][3] = 0ULL;
            }
        }
    }

    // ---- layer 2: 32 W3 tiles ----
    for (int kt = 0; kt < 32; kt++) {
        cp_wait0();
        __syncthreads();
        if (kt < 31) ISSUE(kt + 5);
        mma_tile(wt + (kt & 1) * (16 * 256), ys + kt * 16, 512, acc, t0, jb);
    }

    // ---- epilogue: + b3, store ----
    {
        const float* b3e = b3 + e * H_ + jsel * 256;
        F4 bv0, bv1;
        bv0.v = *(const float4*)&b3e[jb];
        bv1.v = *(const float4*)&b3e[jb + 128];
        float* outb = out + (size_t)b * (T_ * H_) + jsel * 256;
        #pragma unroll
        for (int r = 0; r < 8; r++) {
            float2 a0 = unpk(acc[r][0]), a1 = unpk(acc[r][1]);
            float2 a2 = unpk(acc[r][2]), a3 = unpk(acc[r][3]);
            float4 o0, o1;
            o0.x = a0.x + bv0.f[0]; o0.y = a0.y + bv0.f[1];
            o0.z = a1.x + bv0.f[2]; o0.w = a1.y + bv0.f[3];
            o1.x = a2.x + bv1.f[0]; o1.y = a2.y + bv1.f[1];
            o1.z = a3.x + bv1.f[2]; o1.w = a3.y + bv1.f[3];
            *(float4*)&outb[(size_t)(t0 + r) * 512 + jb]       = o0;
            *(float4*)&outb[(size_t)(t0 + r) * 512 + jb + 128] = o1;
        }
    }
    #undef ISSUE
}

// ---------------------------------------------------------------------------
extern "C" void kernel_launch(void* const* d_in, const int* in_sizes, int n_in,
                              void* d_out, int out_size)
{
    const float* actions = (const float*)d_in[0];
    const float* ts      = (const float*)d_in[1];
    const int*   cat     = (const int*)  d_in[2];
    const float* W1      = (const float*)d_in[3];
    const float* b1      = (const float*)d_in[4];
    const float* W2      = (const float*)d_in[5];
    const float* b2      = (const float*)d_in[6];
    const float* W3      = (const float*)d_in[7];
    const float* b3      = (const float*)d_in[8];
    float*       out     = (float*)d_out;

    const int smem_m1   = (512 * 34 + 2 * 32 * 128) * 4;             // 100 KB
    const int smem_v    = (512 * 16 + 2 * 32 * 128) * 4;             //  64 KB
    const int smem_main = (64 * 512 + 2 * 16 * 256 + 64 * 32) * 4;   // 168 KB

    static int inited = 0;
    if (!inited) {
        cudaFuncSetAttribute(k_m1,   cudaFuncAttributeMaxDynamicSharedMemorySize, smem_m1);
        cudaFuncSetAttribute(k_v,    cudaFuncAttributeMaxDynamicSharedMemorySize, smem_v);
        cudaFuncSetAttribute(k_main, cudaFuncAttributeMaxDynamicSharedMemorySize, smem_main);
        inited = 1;
    }

    k_m1  <<<dim3(E_, 4), 128, smem_m1>>>(W1, W2);
    k_v   <<<dim3(E_, 4), 128, smem_v>>>(ts, cat, W2, b1, b2);
    k_main<<<dim3(B_, 2), 256, smem_main>>>(actions, cat, W3, b3, out);
}